// round 3
// baseline (speedup 1.0000x reference)
#include <cuda_runtime.h>

// ---------------------------------------------------------------------------
// SparseConvolutionDownsample: rulebook sparse conv + BN + LeakyReLU
//   feats [1048576, 64] f32, W [4, 64, 128] f32, gamma/beta [128] f32,
//   in_idx/out_idx [4, 262144] i32, out [262144, 128] f32
// ---------------------------------------------------------------------------

namespace {
constexpr int C_IN   = 64;
constexpr int C_OUT  = 128;
constexpr int PNUM   = 262144;
constexpr int N_OUTR = 262144;
constexpr float BN_EPS = 1e-4f;
constexpr float LEAK   = 0.333f;

constexpr int P_STRIDE = 152;                 // row-warps per (k, half)
constexpr int NUM_T    = (PNUM + P_STRIDE - 1) / P_STRIDE;  // 1725 rows/warp max
constexpr int BATCH    = 8;                   // rows per software-pipeline stage
constexpr int NUM_B    = (NUM_T + BATCH - 1) / BATCH;       // 216 batches
}

// per-channel running sums: [0..127] = sum, [128..255] = sum of squares
__device__ float g_stats[2 * C_OUT];

// packed f32x2 FMA (FFMA2) — PTX-only on sm_103a
__device__ __forceinline__ void ffma2(unsigned long long& d,
                                      unsigned long long a,
                                      unsigned long long b) {
    asm("fma.rn.f32x2 %0, %1, %2, %0;" : "+l"(d) : "l"(a), "l"(b));
}
__device__ __forceinline__ unsigned long long dup2(float x) {
    unsigned u = __float_as_uint(x);
    return ((unsigned long long)u << 32) | u;
}
__device__ __forceinline__ float lo32(unsigned long long v) {
    return __uint_as_float((unsigned)(v & 0xffffffffu));
}
__device__ __forceinline__ float hi32(unsigned long long v) {
    return __uint_as_float((unsigned)(v >> 32));
}

// ---------------------------------------------------------------------------
// Kernel 0: zero the accumulator + zero BN stats
// ---------------------------------------------------------------------------
__global__ void zero_kernel(float4* __restrict__ out) {
    const size_t n = (size_t)N_OUTR * C_OUT / 4;
    const size_t stride = (size_t)gridDim.x * blockDim.x;
    const float4 z = make_float4(0.f, 0.f, 0.f, 0.f);
    for (size_t i = (size_t)blockIdx.x * blockDim.x + threadIdx.x; i < n; i += stride)
        out[i] = z;
    if (blockIdx.x == 0 && threadIdx.x < 2 * C_OUT)
        g_stats[threadIdx.x] = 0.f;
}

// ---------------------------------------------------------------------------
// Kernel 1: warp-autonomous gather -> GEMV -> v4-atomic scatter
//
// Block = 128 threads = 4 warps. Warp gw = blockIdx.x*4 + warp:
//   half = gw & 1 (channels 0..63 / 64..127), p0 = gw >> 1, stride 152.
// Lane owns channel pair (chBase, chBase+1); W[k] column-pair in 128 regs.
// 8-row batches, one batch of gathers in flight ahead of compute:
//   compute slack/batch = 8 x 128 fma-pipe cyc > idx->feats chain (~850 cyc).
// Scatter: lane pairs combine via 2 SHFLs -> even lanes issue ONE
//   red.global.add.v4.f32 (halves atomic lane-op count vs v2).
// ---------------------------------------------------------------------------
__global__ __launch_bounds__(128, 2) void spconv_kernel(
    const float* __restrict__ feats,
    const float* __restrict__ W,
    const int*   __restrict__ in_idx,
    const int*   __restrict__ out_idx,
    float*       __restrict__ out)
{
    // [warp][row-in-batch][col-pair]: {dup(v_2j), dup(v_2j+1)} per entry
    __shared__ ulonglong2 sfeat[4][BATCH][32];   // 16 KB

    const int k    = blockIdx.y;
    const int w    = threadIdx.x >> 5;
    const int lane = threadIdx.x & 31;
    const int gw   = blockIdx.x * 4 + w;     // 0..303
    const int half = gw & 1;
    const int p0   = gw >> 1;                // 0..151
    const int chBase = half * 64 + 2 * lane;

    // ---- W[k] column-pair -> 64 packed f32x2 registers ----
    const float* Wk = W + k * C_IN * C_OUT;
    unsigned long long wreg[C_IN];
#pragma unroll
    for (int i = 0; i < C_IN; i++) {
        float2 ww = *reinterpret_cast<const float2*>(Wk + i * C_OUT + chBase);
        wreg[i] = ((unsigned long long)__float_as_uint(ww.y) << 32)
                |  (unsigned long long)__float_as_uint(ww.x);
    }

    const int* inI  = in_idx  + k * PNUM;
    const int* outI = out_idx + k * PNUM;

    float2 v[BATCH];
    int    oidx[BATCH];

    // gather one row (lane loads its float2 of the feature row); self-guarded
    auto load_row = [&](int t, float2& vv, int& oo) {
        int p = p0 + t * P_STRIDE;
        if (p < PNUM) {
            int ii = __ldg(&inI[p]);
            vv = __ldg(reinterpret_cast<const float2*>(
                     &feats[(size_t)ii * C_IN + 2 * lane]));
            oo = __ldg(&outI[p]);
        } else {
            vv = make_float2(0.f, 0.f);
            oo = 0;
        }
    };

    // prologue: batch 0
#pragma unroll
    for (int u = 0; u < BATCH; u++) load_row(u, v[u], oidx[u]);

    for (int b = 0; b < NUM_B; b++) {
        // publish current batch (duplicated pairs, 16B per lane per row)
#pragma unroll
        for (int u = 0; u < BATCH; u++)
            sfeat[w][u][lane] = make_ulonglong2(dup2(v[u].x), dup2(v[u].y));

        // snapshot out-row ids before the prefetch clobbers them
        int oo[BATCH];
#pragma unroll
        for (int u = 0; u < BATCH; u++) oo[u] = oidx[u];

        __syncwarp();

        // prefetch next batch (latency hidden under this batch's compute)
#pragma unroll
        for (int u = 0; u < BATCH; u++)
            load_row(BATCH * (b + 1) + u, v[u], oidx[u]);

        // compute the staged rows
#pragma unroll
        for (int u = 0; u < BATCH; u++) {
            const int p = p0 + (BATCH * b + u) * P_STRIDE;
            const ulonglong2* sf = sfeat[w][u];
            unsigned long long a0 = 0ull, a1 = 0ull, a2 = 0ull, a3 = 0ull;
#pragma unroll
            for (int j = 0; j < 32; j += 2) {
                ulonglong2 q0 = sf[j];
                ulonglong2 q1 = sf[j + 1];
                ffma2(a0, q0.x, wreg[2 * j]);
                ffma2(a1, q0.y, wreg[2 * j + 1]);
                ffma2(a2, q1.x, wreg[2 * j + 2]);
                ffma2(a3, q1.y, wreg[2 * j + 3]);
            }
            float r0 = (lo32(a0) + lo32(a1)) + (lo32(a2) + lo32(a3));
            float r1 = (hi32(a0) + hi32(a1)) + (hi32(a2) + hi32(a3));

            // pair lanes: even lane picks up odd lane's channel pair -> v4 RED
            float r2 = __shfl_down_sync(0xffffffffu, r0, 1);
            float r3 = __shfl_down_sync(0xffffffffu, r1, 1);
            if (((lane & 1) == 0) && p < PNUM) {
                float* addr = out + (size_t)oo[u] * C_OUT + chBase;
                asm volatile("red.global.add.v4.f32 [%0], {%1, %2, %3, %4};"
                             :: "l"(addr), "f"(r0), "f"(r1), "f"(r2), "f"(r3)
                             : "memory");
            }
        }
        __syncwarp();
    }
}

// ---------------------------------------------------------------------------
// Kernel 2: per-channel sum / sumsq (block-partial + global atomics)
// ---------------------------------------------------------------------------
__global__ void bn_stats_kernel(const float4* __restrict__ out) {
    const int cg = threadIdx.x & 31;   // float4 channel group
    const int rs = threadIdx.x >> 5;   // row sub-slot 0..7
    const int rowsPerBlock = N_OUTR / gridDim.x;
    const int r0 = blockIdx.x * rowsPerBlock;

    float4 s  = make_float4(0.f, 0.f, 0.f, 0.f);
    float4 s2 = make_float4(0.f, 0.f, 0.f, 0.f);
    for (int r = r0 + rs; r < r0 + rowsPerBlock; r += 8) {
        float4 vv = out[(size_t)r * (C_OUT / 4) + cg];
        s.x += vv.x;  s.y += vv.y;  s.z += vv.z;  s.w += vv.w;
        s2.x += vv.x * vv.x;  s2.y += vv.y * vv.y;
        s2.z += vv.z * vv.z;  s2.w += vv.w * vv.w;
    }

    __shared__ float4 shs[256], shq[256];
    shs[threadIdx.x] = s;
    shq[threadIdx.x] = s2;
    __syncthreads();
#pragma unroll
    for (int off = 128; off >= 32; off >>= 1) {
        if (threadIdx.x < off) {
            float4 a = shs[threadIdx.x], b = shs[threadIdx.x + off];
            a.x += b.x; a.y += b.y; a.z += b.z; a.w += b.w;
            shs[threadIdx.x] = a;
            float4 c = shq[threadIdx.x], d = shq[threadIdx.x + off];
            c.x += d.x; c.y += d.y; c.z += d.z; c.w += d.w;
            shq[threadIdx.x] = c;
        }
        __syncthreads();
    }
    if (threadIdx.x < 32) {
        float4 a = shs[threadIdx.x], c = shq[threadIdx.x];
        int c0 = threadIdx.x * 4;
        atomicAdd(&g_stats[c0 + 0], a.x);
        atomicAdd(&g_stats[c0 + 1], a.y);
        atomicAdd(&g_stats[c0 + 2], a.z);
        atomicAdd(&g_stats[c0 + 3], a.w);
        atomicAdd(&g_stats[C_OUT + c0 + 0], c.x);
        atomicAdd(&g_stats[C_OUT + c0 + 1], c.y);
        atomicAdd(&g_stats[C_OUT + c0 + 2], c.z);
        atomicAdd(&g_stats[C_OUT + c0 + 3], c.w);
    }
}

// ---------------------------------------------------------------------------
// Kernel 3: normalize + LeakyReLU (in place, float4)
// ---------------------------------------------------------------------------
__global__ void bn_norm_kernel(float4* __restrict__ out,
                               const float* __restrict__ gamma,
                               const float* __restrict__ beta) {
    __shared__ float sc[C_OUT], sf[C_OUT];
    if (threadIdx.x < C_OUT) {
        int c = threadIdx.x;
        const float inv = 1.f / (float)N_OUTR;
        float mean = g_stats[c] * inv;
        float var  = g_stats[C_OUT + c] * inv - mean * mean;
        float s    = gamma[c] * rsqrtf(var + BN_EPS);
        sc[c] = s;
        sf[c] = beta[c] - mean * s;
    }
    __syncthreads();

    const size_t n = (size_t)N_OUTR * (C_OUT / 4);
    const size_t stride = (size_t)gridDim.x * blockDim.x;
    for (size_t i = (size_t)blockIdx.x * blockDim.x + threadIdx.x; i < n; i += stride) {
        int c0 = ((int)(i & 31)) * 4;
        float4 v = out[i];
        v.x = v.x * sc[c0 + 0] + sf[c0 + 0];
        v.y = v.y * sc[c0 + 1] + sf[c0 + 1];
        v.z = v.z * sc[c0 + 2] + sf[c0 + 2];
        v.w = v.w * sc[c0 + 3] + sf[c0 + 3];
        v.x = (v.x >= 0.f) ? v.x : v.x * LEAK;
        v.y = (v.y >= 0.f) ? v.y : v.y * LEAK;
        v.z = (v.z >= 0.f) ? v.z : v.z * LEAK;
        v.w = (v.w >= 0.f) ? v.w : v.w * LEAK;
        out[i] = v;
    }
}

// ---------------------------------------------------------------------------
// Launch: inputs per metadata order:
//   0 feats, 1 W, 2 gamma, 3 beta, 4 in_idx, 5 out_idx, 6 n_out (ignored)
// ---------------------------------------------------------------------------
extern "C" void kernel_launch(void* const* d_in, const int* in_sizes, int n_in,
                              void* d_out, int out_size) {
    const float* feats   = (const float*)d_in[0];
    const float* W       = (const float*)d_in[1];
    const float* gamma   = (const float*)d_in[2];
    const float* beta    = (const float*)d_in[3];
    const int*   in_idx  = (const int*)d_in[4];
    const int*   out_idx = (const int*)d_in[5];
    float* out = (float*)d_out;

    zero_kernel<<<1024, 256>>>((float4*)out);
    spconv_kernel<<<dim3(76, 4), 128>>>(feats, W, in_idx, out_idx, out);
    bn_stats_kernel<<<256, 256>>>((const float4*)out);
    bn_norm_kernel<<<1024, 256>>>((float4*)out, gamma, beta);
}

// round 4
// speedup vs baseline: 1.2594x; 1.2594x over previous
#include <cuda_runtime.h>

// ---------------------------------------------------------------------------
// SparseConvolutionDownsample: rulebook sparse conv + BN + LeakyReLU
//   feats [1048576, 64] f32, W [4, 64, 128] f32, gamma/beta [128] f32,
//   in_idx/out_idx [4, 262144] i32, out [262144, 128] f32
// ---------------------------------------------------------------------------

namespace {
constexpr int C_IN   = 64;
constexpr int C_OUT  = 128;
constexpr int PNUM   = 262144;
constexpr int N_OUTR = 262144;
constexpr float BN_EPS = 1e-4f;
constexpr float LEAK   = 0.333f;

constexpr int P_STRIDE = 152;                 // row-warps per (k, half)
constexpr int NUM_T    = (PNUM + P_STRIDE - 1) / P_STRIDE;  // 1725 rows/warp max
constexpr int NUM_B    = (NUM_T + 3) / 4;     // 432 batches of 4 rows
}

// per-channel running sums: [0..127] = sum, [128..255] = sum of squares
__device__ float g_stats[2 * C_OUT];

// packed f32x2 FMA (FFMA2) — PTX-only on sm_103a
__device__ __forceinline__ void ffma2(unsigned long long& d,
                                      unsigned long long a,
                                      unsigned long long b) {
    asm("fma.rn.f32x2 %0, %1, %2, %0;" : "+l"(d) : "l"(a), "l"(b));
}
__device__ __forceinline__ unsigned long long dup2(float x) {
    unsigned u = __float_as_uint(x);
    return ((unsigned long long)u << 32) | u;
}
__device__ __forceinline__ float lo32(unsigned long long v) {
    return __uint_as_float((unsigned)(v & 0xffffffffu));
}
__device__ __forceinline__ float hi32(unsigned long long v) {
    return __uint_as_float((unsigned)(v >> 32));
}

// ---------------------------------------------------------------------------
// Kernel 0: zero the accumulator + zero BN stats
// ---------------------------------------------------------------------------
__global__ void zero_kernel(float4* __restrict__ out) {
    const size_t n = (size_t)N_OUTR * C_OUT / 4;
    const size_t stride = (size_t)gridDim.x * blockDim.x;
    const float4 z = make_float4(0.f, 0.f, 0.f, 0.f);
    for (size_t i = (size_t)blockIdx.x * blockDim.x + threadIdx.x; i < n; i += stride)
        out[i] = z;
    if (blockIdx.x == 0 && threadIdx.x < 2 * C_OUT)
        g_stats[threadIdx.x] = 0.f;
}

// no-op launch-slot filler: aligns ncu's "-s 5 -c 1" onto spconv_kernel
__global__ void nop_kernel() {}

// ---------------------------------------------------------------------------
// Kernel 1: warp-autonomous gather -> GEMV -> v4-atomic scatter
//
// Block = 128 threads = 4 warps. Warp gw = blockIdx.x*4 + warp:
//   half = gw & 1 (channels 0..63 / 64..127), p0 = gw >> 1, stride 152.
// Lane owns channel pair (chBase, chBase+1); W[k] column-pair in 128 regs.
// 4-row batches with one-batch-ahead gather prefetch (round-2 structure).
// Scatter: lane pairs combine via 2 SHFLs -> even lanes issue ONE
//   red.global.add.v4.f32 (halves atomic lane-op count vs v2).
// ---------------------------------------------------------------------------
__global__ __launch_bounds__(128, 2) void spconv_kernel(
    const float* __restrict__ feats,
    const float* __restrict__ W,
    const int*   __restrict__ in_idx,
    const int*   __restrict__ out_idx,
    float*       __restrict__ out)
{
    // [warp][row-in-batch][col-pair]: {dup(v_2j), dup(v_2j+1)} per entry
    __shared__ ulonglong2 sfeat[4][4][32];   // 8 KB

    const int k    = blockIdx.y;
    const int w    = threadIdx.x >> 5;
    const int lane = threadIdx.x & 31;
    const int gw   = blockIdx.x * 4 + w;     // 0..303
    const int half = gw & 1;
    const int p0   = gw >> 1;                // 0..151
    const int chBase = half * 64 + 2 * lane;

    // ---- W[k] column-pair -> 64 packed f32x2 registers ----
    const float* Wk = W + k * C_IN * C_OUT;
    unsigned long long wreg[C_IN];
#pragma unroll
    for (int i = 0; i < C_IN; i++) {
        float2 ww = *reinterpret_cast<const float2*>(Wk + i * C_OUT + chBase);
        wreg[i] = ((unsigned long long)__float_as_uint(ww.y) << 32)
                |  (unsigned long long)__float_as_uint(ww.x);
    }

    const int* inI  = in_idx  + k * PNUM;
    const int* outI = out_idx + k * PNUM;

    float2 v[4];
    int    oidx[4];

    // gather one row (lane loads its float2 of the feature row); self-guarded
    auto load_row = [&](int t, float2& vv, int& oo) {
        int p = p0 + t * P_STRIDE;
        if (p < PNUM) {
            int ii = __ldg(&inI[p]);
            vv = __ldg(reinterpret_cast<const float2*>(
                     &feats[(size_t)ii * C_IN + 2 * lane]));
            oo = __ldg(&outI[p]);
        } else {
            vv = make_float2(0.f, 0.f);
            oo = 0;
        }
    };

    // prologue: batch 0
#pragma unroll
    for (int u = 0; u < 4; u++) load_row(u, v[u], oidx[u]);

    for (int b = 0; b < NUM_B; b++) {
        // publish current batch (duplicated pairs, 16B per lane per row)
#pragma unroll
        for (int u = 0; u < 4; u++)
            sfeat[w][u][lane] = make_ulonglong2(dup2(v[u].x), dup2(v[u].y));

        // snapshot out-row ids before the prefetch clobbers them
        int oo0 = oidx[0], oo1 = oidx[1], oo2 = oidx[2], oo3 = oidx[3];

        __syncwarp();

        // prefetch next batch (latency hidden under this batch's compute)
#pragma unroll
        for (int u = 0; u < 4; u++) load_row(4 * (b + 1) + u, v[u], oidx[u]);

        // compute the 4 staged rows
#pragma unroll
        for (int u = 0; u < 4; u++) {
            const int p = p0 + (4 * b + u) * P_STRIDE;
            const ulonglong2* sf = sfeat[w][u];
            unsigned long long a0 = 0ull, a1 = 0ull, a2 = 0ull, a3 = 0ull;
#pragma unroll
            for (int j = 0; j < 32; j += 2) {
                ulonglong2 q0 = sf[j];
                ulonglong2 q1 = sf[j + 1];
                ffma2(a0, q0.x, wreg[2 * j]);
                ffma2(a1, q0.y, wreg[2 * j + 1]);
                ffma2(a2, q1.x, wreg[2 * j + 2]);
                ffma2(a3, q1.y, wreg[2 * j + 3]);
            }
            float r0 = (lo32(a0) + lo32(a1)) + (lo32(a2) + lo32(a3));
            float r1 = (hi32(a0) + hi32(a1)) + (hi32(a2) + hi32(a3));

            // pair lanes: even lane picks up odd lane's channel pair -> v4 RED
            float r2 = __shfl_down_sync(0xffffffffu, r0, 1);
            float r3 = __shfl_down_sync(0xffffffffu, r1, 1);
            int oo = (u == 0) ? oo0 : (u == 1) ? oo1 : (u == 2) ? oo2 : oo3;
            if (((lane & 1) == 0) && p < PNUM) {
                float* addr = out + (size_t)oo * C_OUT + chBase;
                asm volatile("red.global.add.v4.f32 [%0], {%1, %2, %3, %4};"
                             :: "l"(addr), "f"(r0), "f"(r1), "f"(r2), "f"(r3)
                             : "memory");
            }
        }
        __syncwarp();
    }
}

// ---------------------------------------------------------------------------
// Kernel 2: per-channel sum / sumsq (block-partial + global atomics)
// ---------------------------------------------------------------------------
__global__ void bn_stats_kernel(const float4* __restrict__ out) {
    const int cg = threadIdx.x & 31;   // float4 channel group
    const int rs = threadIdx.x >> 5;   // row sub-slot 0..7
    const int rowsPerBlock = N_OUTR / gridDim.x;
    const int r0 = blockIdx.x * rowsPerBlock;

    float4 s  = make_float4(0.f, 0.f, 0.f, 0.f);
    float4 s2 = make_float4(0.f, 0.f, 0.f, 0.f);
    for (int r = r0 + rs; r < r0 + rowsPerBlock; r += 8) {
        float4 vv = out[(size_t)r * (C_OUT / 4) + cg];
        s.x += vv.x;  s.y += vv.y;  s.z += vv.z;  s.w += vv.w;
        s2.x += vv.x * vv.x;  s2.y += vv.y * vv.y;
        s2.z += vv.z * vv.z;  s2.w += vv.w * vv.w;
    }

    __shared__ float4 shs[256], shq[256];
    shs[threadIdx.x] = s;
    shq[threadIdx.x] = s2;
    __syncthreads();
#pragma unroll
    for (int off = 128; off >= 32; off >>= 1) {
        if (threadIdx.x < off) {
            float4 a = shs[threadIdx.x], b = shs[threadIdx.x + off];
            a.x += b.x; a.y += b.y; a.z += b.z; a.w += b.w;
            shs[threadIdx.x] = a;
            float4 c = shq[threadIdx.x], d = shq[threadIdx.x + off];
            c.x += d.x; c.y += d.y; c.z += d.z; c.w += d.w;
            shq[threadIdx.x] = c;
        }
        __syncthreads();
    }
    if (threadIdx.x < 32) {
        float4 a = shs[threadIdx.x], c = shq[threadIdx.x];
        int c0 = threadIdx.x * 4;
        atomicAdd(&g_stats[c0 + 0], a.x);
        atomicAdd(&g_stats[c0 + 1], a.y);
        atomicAdd(&g_stats[c0 + 2], a.z);
        atomicAdd(&g_stats[c0 + 3], a.w);
        atomicAdd(&g_stats[C_OUT + c0 + 0], c.x);
        atomicAdd(&g_stats[C_OUT + c0 + 1], c.y);
        atomicAdd(&g_stats[C_OUT + c0 + 2], c.z);
        atomicAdd(&g_stats[C_OUT + c0 + 3], c.w);
    }
}

// ---------------------------------------------------------------------------
// Kernel 3: normalize + LeakyReLU (in place, float4)
// ---------------------------------------------------------------------------
__global__ void bn_norm_kernel(float4* __restrict__ out,
                               const float* __restrict__ gamma,
                               const float* __restrict__ beta) {
    __shared__ float sc[C_OUT], sf[C_OUT];
    if (threadIdx.x < C_OUT) {
        int c = threadIdx.x;
        const float inv = 1.f / (float)N_OUTR;
        float mean = g_stats[c] * inv;
        float var  = g_stats[C_OUT + c] * inv - mean * mean;
        float s    = gamma[c] * rsqrtf(var + BN_EPS);
        sc[c] = s;
        sf[c] = beta[c] - mean * s;
    }
    __syncthreads();

    const size_t n = (size_t)N_OUTR * (C_OUT / 4);
    const size_t stride = (size_t)gridDim.x * blockDim.x;
    for (size_t i = (size_t)blockIdx.x * blockDim.x + threadIdx.x; i < n; i += stride) {
        int c0 = ((int)(i & 31)) * 4;
        float4 v = out[i];
        v.x = v.x * sc[c0 + 0] + sf[c0 + 0];
        v.y = v.y * sc[c0 + 1] + sf[c0 + 1];
        v.z = v.z * sc[c0 + 2] + sf[c0 + 2];
        v.w = v.w * sc[c0 + 3] + sf[c0 + 3];
        v.x = (v.x >= 0.f) ? v.x : v.x * LEAK;
        v.y = (v.y >= 0.f) ? v.y : v.y * LEAK;
        v.z = (v.z >= 0.f) ? v.z : v.z * LEAK;
        v.w = (v.w >= 0.f) ? v.w : v.w * LEAK;
        out[i] = v;
    }
}

// ---------------------------------------------------------------------------
// Launch: inputs per metadata order:
//   0 feats, 1 W, 2 gamma, 3 beta, 4 in_idx, 5 out_idx, 6 n_out (ignored)
// Two nop launches shift spconv to global launch index 5 so ncu (-s 5 -c 1)
// finally profiles the hot kernel instead of bn_norm.
// ---------------------------------------------------------------------------
extern "C" void kernel_launch(void* const* d_in, const int* in_sizes, int n_in,
                              void* d_out, int out_size) {
    const float* feats   = (const float*)d_in[0];
    const float* W       = (const float*)d_in[1];
    const float* gamma   = (const float*)d_in[2];
    const float* beta    = (const float*)d_in[3];
    const int*   in_idx  = (const int*)d_in[4];
    const int*   out_idx = (const int*)d_in[5];
    float* out = (float*)d_out;

    zero_kernel<<<1024, 256>>>((float4*)out);
    nop_kernel<<<1, 32>>>();
    nop_kernel<<<1, 32>>>();
    spconv_kernel<<<dim3(76, 4), 128>>>(feats, W, in_idx, out_idx, out);
    bn_stats_kernel<<<256, 256>>>((const float4*)out);
    bn_norm_kernel<<<1024, 256>>>((float4*)out, gamma, beta);
}

// round 5
// speedup vs baseline: 1.3330x; 1.0585x over previous
#include <cuda_runtime.h>

// ---------------------------------------------------------------------------
// SparseConvolutionDownsample: rulebook sparse conv + BN + LeakyReLU
//   feats [1048576, 64] f32, W [4, 64, 128] f32, gamma/beta [128] f32,
//   in_idx/out_idx [4, 262144] i32, out [262144, 128] f32
// ---------------------------------------------------------------------------

namespace {
constexpr int C_IN   = 64;
constexpr int C_OUT  = 128;
constexpr int PNUM   = 262144;
constexpr int N_OUTR = 262144;
constexpr float BN_EPS = 1e-4f;
constexpr float LEAK   = 0.333f;

constexpr int P_STRIDE = 152;                 // row-warps per (k, half)
constexpr int NUM_T    = (PNUM + P_STRIDE - 1) / P_STRIDE;  // 1725 rows/warp max
constexpr int NUM_B    = (NUM_T + 3) / 4;     // 432 batches of 4 rows
}

// per-channel running sums: [0..127] = sum, [128..255] = sum of squares
__device__ float g_stats[2 * C_OUT];

// packed f32x2 ops — PTX-only on sm_103a
__device__ __forceinline__ void ffma2(unsigned long long& d,
                                      unsigned long long a,
                                      unsigned long long b) {
    asm("fma.rn.f32x2 %0, %1, %2, %0;" : "+l"(d) : "l"(a), "l"(b));
}
__device__ __forceinline__ unsigned long long add2(unsigned long long a,
                                                   unsigned long long b) {
    unsigned long long d;
    asm("add.rn.f32x2 %0, %1, %2;" : "=l"(d) : "l"(a), "l"(b));
    return d;
}
__device__ __forceinline__ unsigned long long pack2(float x, float y) {
    return ((unsigned long long)__float_as_uint(y) << 32)
         |  (unsigned long long)__float_as_uint(x);
}
__device__ __forceinline__ float lo32(unsigned long long v) {
    return __uint_as_float((unsigned)(v & 0xffffffffu));
}
__device__ __forceinline__ float hi32(unsigned long long v) {
    return __uint_as_float((unsigned)(v >> 32));
}

// ---------------------------------------------------------------------------
// Kernel 0: zero the accumulator + zero BN stats
// ---------------------------------------------------------------------------
__global__ void zero_kernel(float4* __restrict__ out) {
    const size_t n = (size_t)N_OUTR * C_OUT / 4;
    const size_t stride = (size_t)gridDim.x * blockDim.x;
    const float4 z = make_float4(0.f, 0.f, 0.f, 0.f);
    for (size_t i = (size_t)blockIdx.x * blockDim.x + threadIdx.x; i < n; i += stride)
        out[i] = z;
    if (blockIdx.x == 0 && threadIdx.x < 2 * C_OUT)
        g_stats[threadIdx.x] = 0.f;
}

// no-op launch-slot filler: aligns ncu's "-s 5 -c 1" onto spconv_kernel
__global__ void nop_kernel() {}

// ---------------------------------------------------------------------------
// Kernel 1: warp-autonomous gather -> GEMV -> v4-atomic scatter
//
// K-dim-packed FFMA2 formulation: each f32x2 accumulator holds the even-i /
// odd-i partial sums of ONE output channel, so the multiplicand is the RAW
// staged pair {f[2j], f[2j+1]} — no duplicated staging. Per row per warp:
//   16 x LDS.128 (4 raw features) + 64 x FFMA2 on 4 chains (2 channels x 2
//   K-phases), folded with add.rn.f32x2 at the end.
// Rows staged 4 per batch, one batch of gathers prefetched ahead.
// Scatter: lane pairs combine via 2 SHFLs -> even lanes issue ONE
//   red.global.add.v4.f32.
// ---------------------------------------------------------------------------
__global__ __launch_bounds__(128, 2) void spconv_kernel(
    const float* __restrict__ feats,
    const float* __restrict__ W,
    const int*   __restrict__ in_idx,
    const int*   __restrict__ out_idx,
    float*       __restrict__ out)
{
    // [warp][row-in-batch][lane]: raw float2 {f[2*lane], f[2*lane+1]}  (4 KB)
    __shared__ __align__(16) unsigned long long sfeat[4][4][32];

    const int k    = blockIdx.y;
    const int w    = threadIdx.x >> 5;
    const int lane = threadIdx.x & 31;
    const int gw   = blockIdx.x * 4 + w;     // 0..303
    const int half = gw & 1;
    const int p0   = gw >> 1;                // 0..151
    const int chBase = half * 64 + 2 * lane;

    // ---- W[k] columns chBase, chBase+1 -> K-pair-packed registers ----
    //   w0[j] = {W[2j][c0], W[2j+1][c0]},  w1[j] = {W[2j][c1], W[2j+1][c1]}
    const float* Wk = W + k * C_IN * C_OUT;
    unsigned long long w0[C_IN / 2], w1[C_IN / 2];
#pragma unroll
    for (int j = 0; j < C_IN / 2; j++) {
        float2 wa = *reinterpret_cast<const float2*>(Wk + (2 * j)     * C_OUT + chBase);
        float2 wb = *reinterpret_cast<const float2*>(Wk + (2 * j + 1) * C_OUT + chBase);
        w0[j] = pack2(wa.x, wb.x);
        w1[j] = pack2(wa.y, wb.y);
    }

    const int* inI  = in_idx  + k * PNUM;
    const int* outI = out_idx + k * PNUM;

    float2 v[4];
    int    oidx[4];

    // gather one row (lane loads its float2 of the feature row); self-guarded
    auto load_row = [&](int t, float2& vv, int& oo) {
        int p = p0 + t * P_STRIDE;
        if (p < PNUM) {
            int ii = __ldg(&inI[p]);
            vv = __ldg(reinterpret_cast<const float2*>(
                     &feats[(size_t)ii * C_IN + 2 * lane]));
            oo = __ldg(&outI[p]);
        } else {
            vv = make_float2(0.f, 0.f);
            oo = 0;
        }
    };

    // prologue: batch 0
#pragma unroll
    for (int u = 0; u < 4; u++) load_row(u, v[u], oidx[u]);

    for (int b = 0; b < NUM_B; b++) {
        // publish current batch (raw pairs, 8B per lane per row)
#pragma unroll
        for (int u = 0; u < 4; u++)
            sfeat[w][u][lane] = pack2(v[u].x, v[u].y);

        // snapshot out-row ids before the prefetch clobbers them
        int oo0 = oidx[0], oo1 = oidx[1], oo2 = oidx[2], oo3 = oidx[3];

        __syncwarp();

        // prefetch next batch (latency hidden under this batch's compute)
#pragma unroll
        for (int u = 0; u < 4; u++) load_row(4 * (b + 1) + u, v[u], oidx[u]);

        // compute the 4 staged rows
#pragma unroll
        for (int u = 0; u < 4; u++) {
            const int p = p0 + (4 * b + u) * P_STRIDE;
            const ulonglong2* sf =
                reinterpret_cast<const ulonglong2*>(sfeat[w][u]);   // 16 entries
            unsigned long long a00 = 0ull, a01 = 0ull, a10 = 0ull, a11 = 0ull;
#pragma unroll
            for (int t = 0; t < 16; t++) {
                ulonglong2 q = sf[t];          // {f[4t..4t+1]}, {f[4t+2..4t+3]}
                ffma2(a00, q.x, w0[2 * t]);
                ffma2(a10, q.x, w1[2 * t]);
                ffma2(a01, q.y, w0[2 * t + 1]);
                ffma2(a11, q.y, w1[2 * t + 1]);
            }
            unsigned long long s0 = add2(a00, a01);
            unsigned long long s1 = add2(a10, a11);
            float r0 = lo32(s0) + hi32(s0);    // channel chBase
            float r1 = lo32(s1) + hi32(s1);    // channel chBase+1

            // pair lanes: even lane picks up odd lane's channel pair -> v4 RED
            float r2 = __shfl_down_sync(0xffffffffu, r0, 1);
            float r3 = __shfl_down_sync(0xffffffffu, r1, 1);
            int oo = (u == 0) ? oo0 : (u == 1) ? oo1 : (u == 2) ? oo2 : oo3;
            if (((lane & 1) == 0) && p < PNUM) {
                float* addr = out + (size_t)oo * C_OUT + chBase;
                asm volatile("red.global.add.v4.f32 [%0], {%1, %2, %3, %4};"
                             :: "l"(addr), "f"(r0), "f"(r1), "f"(r2), "f"(r3)
                             : "memory");
            }
        }
        __syncwarp();
    }
}

// ---------------------------------------------------------------------------
// Kernel 2: per-channel sum / sumsq (block-partial + global atomics)
// ---------------------------------------------------------------------------
__global__ void bn_stats_kernel(const float4* __restrict__ out) {
    const int cg = threadIdx.x & 31;   // float4 channel group
    const int rs = threadIdx.x >> 5;   // row sub-slot 0..7
    const int rowsPerBlock = N_OUTR / gridDim.x;
    const int r0 = blockIdx.x * rowsPerBlock;

    float4 s  = make_float4(0.f, 0.f, 0.f, 0.f);
    float4 s2 = make_float4(0.f, 0.f, 0.f, 0.f);
    for (int r = r0 + rs; r < r0 + rowsPerBlock; r += 8) {
        float4 vv = out[(size_t)r * (C_OUT / 4) + cg];
        s.x += vv.x;  s.y += vv.y;  s.z += vv.z;  s.w += vv.w;
        s2.x += vv.x * vv.x;  s2.y += vv.y * vv.y;
        s2.z += vv.z * vv.z;  s2.w += vv.w * vv.w;
    }

    __shared__ float4 shs[256], shq[256];
    shs[threadIdx.x] = s;
    shq[threadIdx.x] = s2;
    __syncthreads();
#pragma unroll
    for (int off = 128; off >= 32; off >>= 1) {
        if (threadIdx.x < off) {
            float4 a = shs[threadIdx.x], b = shs[threadIdx.x + off];
            a.x += b.x; a.y += b.y; a.z += b.z; a.w += b.w;
            shs[threadIdx.x] = a;
            float4 c = shq[threadIdx.x], d = shq[threadIdx.x + off];
            c.x += d.x; c.y += d.y; c.z += d.z; c.w += d.w;
            shq[threadIdx.x] = c;
        }
        __syncthreads();
    }
    if (threadIdx.x < 32) {
        float4 a = shs[threadIdx.x], c = shq[threadIdx.x];
        int c0 = threadIdx.x * 4;
        atomicAdd(&g_stats[c0 + 0], a.x);
        atomicAdd(&g_stats[c0 + 1], a.y);
        atomicAdd(&g_stats[c0 + 2], a.z);
        atomicAdd(&g_stats[c0 + 3], a.w);
        atomicAdd(&g_stats[C_OUT + c0 + 0], c.x);
        atomicAdd(&g_stats[C_OUT + c0 + 1], c.y);
        atomicAdd(&g_stats[C_OUT + c0 + 2], c.z);
        atomicAdd(&g_stats[C_OUT + c0 + 3], c.w);
    }
}

// ---------------------------------------------------------------------------
// Kernel 3: normalize + LeakyReLU (in place, float4)
// ---------------------------------------------------------------------------
__global__ void bn_norm_kernel(float4* __restrict__ out,
                               const float* __restrict__ gamma,
                               const float* __restrict__ beta) {
    __shared__ float sc[C_OUT], sf[C_OUT];
    if (threadIdx.x < C_OUT) {
        int c = threadIdx.x;
        const float inv = 1.f / (float)N_OUTR;
        float mean = g_stats[c] * inv;
        float var  = g_stats[C_OUT + c] * inv - mean * mean;
        float s    = gamma[c] * rsqrtf(var + BN_EPS);
        sc[c] = s;
        sf[c] = beta[c] - mean * s;
    }
    __syncthreads();

    const size_t n = (size_t)N_OUTR * (C_OUT / 4);
    const size_t stride = (size_t)gridDim.x * blockDim.x;
    for (size_t i = (size_t)blockIdx.x * blockDim.x + threadIdx.x; i < n; i += stride) {
        int c0 = ((int)(i & 31)) * 4;
        float4 v = out[i];
        v.x = v.x * sc[c0 + 0] + sf[c0 + 0];
        v.y = v.y * sc[c0 + 1] + sf[c0 + 1];
        v.z = v.z * sc[c0 + 2] + sf[c0 + 2];
        v.w = v.w * sc[c0 + 3] + sf[c0 + 3];
        v.x = (v.x >= 0.f) ? v.x : v.x * LEAK;
        v.y = (v.y >= 0.f) ? v.y : v.y * LEAK;
        v.z = (v.z >= 0.f) ? v.z : v.z * LEAK;
        v.w = (v.w >= 0.f) ? v.w : v.w * LEAK;
        out[i] = v;
    }
}

// ---------------------------------------------------------------------------
// Launch: inputs per metadata order:
//   0 feats, 1 W, 2 gamma, 3 beta, 4 in_idx, 5 out_idx, 6 n_out (ignored)
// ---------------------------------------------------------------------------
extern "C" void kernel_launch(void* const* d_in, const int* in_sizes, int n_in,
                              void* d_out, int out_size) {
    const float* feats   = (const float*)d_in[0];
    const float* W       = (const float*)d_in[1];
    const float* gamma   = (const float*)d_in[2];
    const float* beta    = (const float*)d_in[3];
    const int*   in_idx  = (const int*)d_in[4];
    const int*   out_idx = (const int*)d_in[5];
    float* out = (float*)d_out;

    zero_kernel<<<1024, 256>>>((float4*)out);
    nop_kernel<<<1, 32>>>();
    nop_kernel<<<1, 32>>>();
    spconv_kernel<<<dim3(76, 4), 128>>>(feats, W, in_idx, out_idx, out);
    bn_stats_kernel<<<256, 256>>>((const float4*)out);
    bn_norm_kernel<<<1024, 256>>>((float4*)out, gamma, beta);
}